// round 12
// baseline (speedup 1.0000x reference)
#include <cuda_runtime.h>
#include <cuda_fp16.h>
#include <cstdint>

// Problem constants
#define B_   4
#define N_   24
#define C_   256
#define H_   100
#define W_   100
#define OUT_ 7
#define P_   276                      // N*(N-1)/2
#define CH_  (C_ * OUT_ * OUT_)       // 12544 floats per full [C,7,7] chunk
#define HCH_ (CH_ / 2)                // 6272 floats per half-channel chunk
#define HW_  (H_ * W_)
#define SCALE_ 0.25f
#define NROIS_ (N_ + P_)              // 300 rois per batch
#define NV_   (HCH_ / 4)              // 1568 float4 per half tile
#define RPT_  7                       // ceil(1568/256) staging slots

// fp16 NHWC scratch for features
__device__ __half g_nhwc_h[(size_t)B_ * HW_ * C_];

__device__ __forceinline__ void stcs4(float4* p, float4 v) {
    asm volatile("st.global.cs.v4.f32 [%0], {%1,%2,%3,%4};"
                 :: "l"(p), "f"(v.x), "f"(v.y), "f"(v.z), "f"(v.w) : "memory");
}

// ---------------------------------------------------------------------------
// Kernel 1: NCHW fp32 -> NHWC fp16 transpose.
// ---------------------------------------------------------------------------
__global__ void nchw_to_nhwc_kernel(const float* __restrict__ in) {
    __shared__ float tile[32][33];
    const int b   = blockIdx.z;
    const int c0  = blockIdx.y * 32;
    const int hw0 = blockIdx.x * 32;
    const int tx = threadIdx.x, ty = threadIdx.y;   // (32, 8)
    const int tid = ty * 32 + tx;

    const float* src = in + (size_t)b * C_ * HW_;
#pragma unroll
    for (int i = 0; i < 32; i += 8) {
        const int c  = c0 + ty + i;
        const int hw = hw0 + tx;
        float v = 0.0f;
        if (hw < HW_) v = src[(size_t)c * HW_ + hw];
        tile[ty + i][tx] = v;
    }
    __syncthreads();

    // Store side: each thread converts 4 channels of one hw to fp16 (8B).
    const int tx8 = tid & 7;     // channel quad 0..7
    const int tyy = tid >> 3;    // hw within tile
    const int hw  = hw0 + tyy;
    if (hw < HW_) {
        struct __align__(8) H4 { __half2 a, b; } h4;
        h4.a = __floats2half2_rn(tile[4 * tx8 + 0][tyy], tile[4 * tx8 + 1][tyy]);
        h4.b = __floats2half2_rn(tile[4 * tx8 + 2][tyy], tile[4 * tx8 + 3][tyy]);
        __half* dst = g_nhwc_h + (size_t)b * HW_ * C_;
        *reinterpret_cast<H4*>(&dst[(size_t)hw * C_ + c0 + 4 * tx8]) = h4;
    }
}

// ---------------------------------------------------------------------------
// Kernel 2: TWO CTAs per roi (one per 128-channel half). 256 threads.
//  Phase B: fp16 NHWC feature taps. Thread owns 8 channels (c8 = tid&15),
//           one LDG.128.NC per tap (16B = 8 halfs); 16-lane half-warp reads
//           256B contiguous. fp32 accumulate.
//  Phase C: register-staged float4 streaming-store fan-out (best of R8).
// ---------------------------------------------------------------------------
__global__ __launch_bounds__(256, 5) void roi_pair_kernel(
    const float* __restrict__ boxes,   // [B, N, 4] xyxy, image coords
    float* __restrict__ out)           // [B*P, 3, C, 7, 7]
{
    __shared__ __align__(16) float pooled[HCH_];
    __shared__ int   sy0[14], sy1[14], sx0[14], sx1[14];
    __shared__ float sly[14], shy[14], slx[14], shx[14];

    const int bid   = blockIdx.x;
    const int tid   = threadIdx.x;
    const int r     = bid >> 1;      // roi id 0..1199 (objects first)
    const int chalf = bid & 1;       // channel half

    int b, m;  // batch, roi index within batch (m < N_: object, else union)
    if (r < B_ * N_) { b = r / N_; m = r % N_; }
    else { const int u = r - B_ * N_; b = u / P_; m = N_ + (u % P_); }

    // Separable sample tables: tid 0..13 -> x, 14..27 -> y.
    if (tid < 28) {
        float x1, y1, x2, y2;
        if (m < N_) {
            const float* bx = boxes + ((size_t)b * N_ + m) * 4;
            x1 = bx[0]; y1 = bx[1]; x2 = bx[2]; y2 = bx[3];
        } else {
            int p = m - N_;
            int i = 0, rem = p, cnt = N_ - 1;
            while (rem >= cnt) { rem -= cnt; ++i; --cnt; }
            const int j = i + 1 + rem;
            const float* ba = boxes + ((size_t)b * N_ + i) * 4;
            const float* bb = boxes + ((size_t)b * N_ + j) * 4;
            x1 = fminf(ba[0], bb[0]);
            y1 = fminf(ba[1], bb[1]);
            x2 = fmaxf(ba[2], bb[2]);
            y2 = fmaxf(ba[3], bb[3]);
        }
        const int  d   = tid % 14;
        const bool isY = (tid >= 14);
        const float c1 = (isY ? y1 : x1) * SCALE_;
        const float c2 = (isY ? y2 : x2) * SCALE_;
        const float sz  = fmaxf(c2 - c1, 1.0f);
        const float bsz = sz * (1.0f / OUT_);
        const float g = (float)(d >> 1) + ((float)(d & 1) + 0.5f) * 0.5f;
        const float X = c1 + g * bsz;
        const int   lim = isY ? H_ : W_;
        const bool  valid = (X > -1.0f) && (X < (float)lim);
        const float Xc  = fminf(fmaxf(X, 0.0f), (float)(lim - 1));
        const float x0f = floorf(Xc);
        float lx = Xc - x0f;
        float hx = 1.0f - lx;
        if (!valid) { lx = 0.0f; hx = 0.0f; }
        const int t0 = (int)x0f;
        const int t1 = min(t0 + 1, lim - 1);
        if (isY) { sy0[d] = t0; sy1[d] = t1; sly[d] = lx; shy[d] = hx; }
        else     { sx0[d] = t0; sx1[d] = t1; slx[d] = lx; shx[d] = hx; }
    }
    __syncthreads();

    // Phase B.
    const int c8   = tid & 15;           // 8-channel group 0..15 (128ch half)
    const int slot = tid >> 4;           // 0..15
    const int quad = (tid >> 2) & 3;     // 4-lane quad
    const int res  = (slot + quad) & 15; // bin residue mod 16 (skewed)
    const __half* __restrict__ feath =
        g_nhwc_h + (size_t)b * HW_ * C_ + chalf * (C_ / 2) + c8 * 8;

#pragma unroll 1
    for (int t = 0; t < 4; ++t) {
        const int bin = 16 * t + res;
        if (bin >= OUT_ * OUT_) break;
        const int py = bin / OUT_;
        const int px = bin - py * OUT_;
        float acc[8];
#pragma unroll
        for (int k = 0; k < 8; ++k) acc[k] = 0.0f;
#pragma unroll
        for (int sy = 0; sy < 2; ++sy) {
            const int   yi = 2 * py + sy;
            const int   y0 = sy0[yi], y1 = sy1[yi];
            const float ly = sly[yi], hy = shy[yi];
            const int r0 = y0 * W_;
            const int r1 = y1 * W_;
#pragma unroll
            for (int sx = 0; sx < 2; ++sx) {
                const int   xi = 2 * px + sx;
                const int   x0 = sx0[xi], x1 = sx1[xi];
                const float lx = slx[xi], hx = shx[xi];
                const uint4 u00 = __ldg(reinterpret_cast<const uint4*>(feath + (size_t)(r0 + x0) * C_));
                const uint4 u01 = __ldg(reinterpret_cast<const uint4*>(feath + (size_t)(r0 + x1) * C_));
                const uint4 u10 = __ldg(reinterpret_cast<const uint4*>(feath + (size_t)(r1 + x0) * C_));
                const uint4 u11 = __ldg(reinterpret_cast<const uint4*>(feath + (size_t)(r1 + x1) * C_));
                const float w00 = hy * hx, w01 = hy * lx, w10 = ly * hx, w11 = ly * lx;
                const uint32_t* p00 = &u00.x;
                const uint32_t* p01 = &u01.x;
                const uint32_t* p10 = &u10.x;
                const uint32_t* p11 = &u11.x;
#pragma unroll
                for (int h2 = 0; h2 < 4; ++h2) {
                    const float2 f00 = __half22float2(*reinterpret_cast<const __half2*>(&p00[h2]));
                    const float2 f01 = __half22float2(*reinterpret_cast<const __half2*>(&p01[h2]));
                    const float2 f10 = __half22float2(*reinterpret_cast<const __half2*>(&p10[h2]));
                    const float2 f11 = __half22float2(*reinterpret_cast<const __half2*>(&p11[h2]));
                    acc[2 * h2 + 0] += w00 * f00.x + w01 * f01.x + w10 * f10.x + w11 * f11.x;
                    acc[2 * h2 + 1] += w00 * f00.y + w01 * f01.y + w10 * f10.y + w11 * f11.y;
                }
            }
        }
        const int base = (8 * c8) * 49 + bin;
#pragma unroll
        for (int k = 0; k < 8; ++k)
            pooled[base + 49 * k] = acc[k] * 0.25f;
    }
    __syncthreads();

    // Phase C: stage half-tile into registers once, streaming STG.128 fan-out.
    const float4* __restrict__ psrc = reinterpret_cast<const float4*>(pooled);
    float4 stage[RPT_];
#pragma unroll
    for (int k = 0; k < RPT_; ++k) {
        const int idx = tid + k * 256;
        if (idx < NV_) stage[k] = psrc[idx];
    }

    float4* outv = reinterpret_cast<float4*>(out);
    const int hoff = chalf * NV_;

    if (m < N_) {
#pragma unroll 1
        for (int q = 0; q < N_ - 1; ++q) {
            int p, slot_o;
            const int hi = N_ - 1 - m;
            if (q < hi) {
                const int j = m + 1 + q;
                p = m * (N_ - 1) - (m * (m - 1)) / 2 + (j - m - 1);
                slot_o = 0;
            } else {
                const int i = q - hi;
                p = i * (N_ - 1) - (i * (i - 1)) / 2 + (m - i - 1);
                slot_o = 1;
            }
            float4* dst = outv + (((size_t)b * P_ + p) * 3 + slot_o) * (CH_ / 4) + hoff;
#pragma unroll
            for (int k = 0; k < RPT_; ++k) {
                const int idx = tid + k * 256;
                if (idx < NV_) stcs4(&dst[idx], stage[k]);
            }
        }
    } else {
        const int p = m - N_;
        float4* dst = outv + (((size_t)b * P_ + p) * 3 + 2) * (CH_ / 4) + hoff;
#pragma unroll
        for (int k = 0; k < RPT_; ++k) {
            const int idx = tid + k * 256;
            if (idx < NV_) stcs4(&dst[idx], stage[k]);
        }
    }
}

// ---------------------------------------------------------------------------
extern "C" void kernel_launch(void* const* d_in, const int* in_sizes, int n_in,
                              void* d_out, int out_size) {
    const float* features = (const float*)d_in[0];  // [B,C,H,W] float32
    const float* boxes    = (const float*)d_in[1];  // [B,N,4]   float32
    float* out = (float*)d_out;

    dim3 tgrid((HW_ + 31) / 32, C_ / 32, B_);
    nchw_to_nhwc_kernel<<<tgrid, dim3(32, 8)>>>(features);

    const int nblocks = 2 * B_ * NROIS_;   // 2400: 192 object CTAs first
    roi_pair_kernel<<<nblocks, 256>>>(boxes, out);
}

// round 13
// speedup vs baseline: 1.1786x; 1.1786x over previous
#include <cuda_runtime.h>
#include <cstdint>

// Problem constants
#define B_   4
#define N_   24
#define C_   256
#define H_   100
#define W_   100
#define OUT_ 7
#define P_   276                      // N*(N-1)/2
#define CH_  (C_ * OUT_ * OUT_)       // 12544 floats per full [C,7,7] chunk
#define HCH_ (CH_ / 2)                // 6272 floats per half-channel chunk
#define HW_  (H_ * W_)
#define SCALE_ 0.25f
#define NROIS_ (N_ + P_)              // 300 rois per batch
#define NV_   (HCH_ / 4)              // 1568 float4 per half tile
#define RPT_  7                       // ceil(1568/256) staging slots

// NHWC scratch for features
__device__ float g_nhwc[(size_t)B_ * HW_ * C_];

__device__ __forceinline__ void stcs4(float4* p, float4 v) {
    asm volatile("st.global.cs.v4.f32 [%0], {%1,%2,%3,%4};"
                 :: "l"(p), "f"(v.x), "f"(v.y), "f"(v.z), "f"(v.w) : "memory");
}

// ---------------------------------------------------------------------------
// Kernel 1: NCHW -> NHWC transpose, float4 stores.
// ---------------------------------------------------------------------------
__global__ void nchw_to_nhwc_kernel(const float* __restrict__ in) {
    __shared__ float tile[32][33];
    const int b   = blockIdx.z;
    const int c0  = blockIdx.y * 32;
    const int hw0 = blockIdx.x * 32;
    const int tx = threadIdx.x, ty = threadIdx.y;   // (32, 8)
    const int tid = ty * 32 + tx;

    const float* src = in + (size_t)b * C_ * HW_;
#pragma unroll
    for (int i = 0; i < 32; i += 8) {
        const int c  = c0 + ty + i;
        const int hw = hw0 + tx;
        float v = 0.0f;
        if (hw < HW_) v = src[(size_t)c * HW_ + hw];
        tile[ty + i][tx] = v;
    }
    __syncthreads();

    const int tx8 = tid & 7;     // float4 channel group
    const int tyy = tid >> 3;    // hw within tile
    const int hw  = hw0 + tyy;
    if (hw < HW_) {
        float4 v;
        v.x = tile[4 * tx8 + 0][tyy];
        v.y = tile[4 * tx8 + 1][tyy];
        v.z = tile[4 * tx8 + 2][tyy];
        v.w = tile[4 * tx8 + 3][tyy];
        float* dst = g_nhwc + (size_t)b * HW_ * C_;
        *reinterpret_cast<float4*>(&dst[(size_t)hw * C_ + c0 + 4 * tx8]) = v;
    }
}

// ---------------------------------------------------------------------------
// Phase-B helper: accumulate one bin's 16 taps.
// ---------------------------------------------------------------------------
__device__ __forceinline__ float4 bin_taps(
    int bin, const float4* __restrict__ feat,
    const int* sy0, const int* sy1, const int* sx0, const int* sx1,
    const float* sly, const float* shy, const float* slx, const float* shx)
{
    const int py = bin / OUT_;
    const int px = bin - py * OUT_;
    float4 acc = make_float4(0.f, 0.f, 0.f, 0.f);
#pragma unroll
    for (int sy = 0; sy < 2; ++sy) {
        const int   yi = 2 * py + sy;
        const int   y0 = sy0[yi], y1 = sy1[yi];
        const float ly = sly[yi], hy = shy[yi];
        const int r0 = y0 * W_;
        const int r1 = y1 * W_;
#pragma unroll
        for (int sx = 0; sx < 2; ++sx) {
            const int   xi = 2 * px + sx;
            const int   x0 = sx0[xi], x1 = sx1[xi];
            const float lx = slx[xi], hx = shx[xi];
            const float4 f00 = feat[(size_t)(r0 + x0) * 64];
            const float4 f01 = feat[(size_t)(r0 + x1) * 64];
            const float4 f10 = feat[(size_t)(r1 + x0) * 64];
            const float4 f11 = feat[(size_t)(r1 + x1) * 64];
            const float w00 = hy * hx, w01 = hy * lx, w10 = ly * hx, w11 = ly * lx;
            acc.x += w00 * f00.x + w01 * f01.x + w10 * f10.x + w11 * f11.x;
            acc.y += w00 * f00.y + w01 * f01.y + w10 * f10.y + w11 * f11.y;
            acc.z += w00 * f00.z + w01 * f01.z + w10 * f10.z + w11 * f11.z;
            acc.w += w00 * f00.w + w01 * f01.w + w10 * f10.w + w11 * f11.w;
        }
    }
    return acc;
}

// ---------------------------------------------------------------------------
// Kernel 2: TWO CTAs per roi (one per 128-channel half). 256 threads.
//  Phase B: bins 8t+res for t=0..5 are ALWAYS < 48 -> guard-free fully
//           unrolled loop (ptxas pipelines loads across bins, MLP ~32);
//           tail bin 48 handled by res==0 threads only.
//  Phase C: register-staged float4 streaming-store fan-out.
// ---------------------------------------------------------------------------
__global__ __launch_bounds__(256, 4) void roi_pair_kernel(
    const float* __restrict__ boxes,   // [B, N, 4] xyxy, image coords
    float* __restrict__ out)           // [B*P, 3, C, 7, 7]
{
    __shared__ __align__(16) float pooled[HCH_];
    __shared__ int   sy0[14], sy1[14], sx0[14], sx1[14];
    __shared__ float sly[14], shy[14], slx[14], shx[14];

    const int bid  = blockIdx.x;
    const int tid  = threadIdx.x;
    const int r    = bid >> 1;       // roi id 0..1199 (objects first)
    const int half = bid & 1;        // channel half

    int b, m;  // batch, roi index within batch (m < N_: object, else union)
    if (r < B_ * N_) { b = r / N_; m = r % N_; }
    else { const int u = r - B_ * N_; b = u / P_; m = N_ + (u % P_); }

    // Separable sample tables: tid 0..13 -> x, 14..27 -> y.
    if (tid < 28) {
        float x1, y1, x2, y2;
        if (m < N_) {
            const float* bx = boxes + ((size_t)b * N_ + m) * 4;
            x1 = bx[0]; y1 = bx[1]; x2 = bx[2]; y2 = bx[3];
        } else {
            int p = m - N_;
            int i = 0, rem = p, cnt = N_ - 1;
            while (rem >= cnt) { rem -= cnt; ++i; --cnt; }
            const int j = i + 1 + rem;
            const float* ba = boxes + ((size_t)b * N_ + i) * 4;
            const float* bb = boxes + ((size_t)b * N_ + j) * 4;
            x1 = fminf(ba[0], bb[0]);
            y1 = fminf(ba[1], bb[1]);
            x2 = fmaxf(ba[2], bb[2]);
            y2 = fmaxf(ba[3], bb[3]);
        }
        const int  d   = tid % 14;
        const bool isY = (tid >= 14);
        const float c1 = (isY ? y1 : x1) * SCALE_;
        const float c2 = (isY ? y2 : x2) * SCALE_;
        const float sz  = fmaxf(c2 - c1, 1.0f);
        const float bsz = sz * (1.0f / OUT_);
        const float g = (float)(d >> 1) + ((float)(d & 1) + 0.5f) * 0.5f;
        const float X = c1 + g * bsz;
        const int   lim = isY ? H_ : W_;
        const bool  valid = (X > -1.0f) && (X < (float)lim);
        const float Xc  = fminf(fmaxf(X, 0.0f), (float)(lim - 1));
        const float x0f = floorf(Xc);
        float lx = Xc - x0f;
        float hx = 1.0f - lx;
        if (!valid) { lx = 0.0f; hx = 0.0f; }
        const int t0 = (int)x0f;
        const int t1 = min(t0 + 1, lim - 1);
        if (isY) { sy0[d] = t0; sy1[d] = t1; sly[d] = lx; shy[d] = hx; }
        else     { sx0[d] = t0; sx1[d] = t1; slx[d] = lx; shx[d] = hx; }
    }
    __syncthreads();

    // Phase B.
    const int c4   = tid & 31;          // local float4 channel group 0..31
    const int slot = tid >> 5;          // warp id 0..7
    const int oct  = (tid >> 3) & 3;    // lane octet within warp
    const int res  = (slot + oct) & 7;  // bin residue mod 8 (skewed)
    const float4* __restrict__ feat =
        reinterpret_cast<const float4*>(g_nhwc) +
        (size_t)b * HW_ * (C_ / 4) + half * 32 + c4;

    // Bins 8t+res for t in [0,6): max 5*8+7=47 < 48 -> always valid.
#pragma unroll
    for (int t = 0; t < 6; ++t) {
        const int bin = 8 * t + res;
        const float4 acc = bin_taps(bin, feat, sy0, sy1, sx0, sx1,
                                    sly, shy, slx, shx);
        const int base = (4 * c4) * 49 + bin;   // conflict-free STS
        pooled[base]       = acc.x * 0.25f;
        pooled[base + 49]  = acc.y * 0.25f;
        pooled[base + 98]  = acc.z * 0.25f;
        pooled[base + 147] = acc.w * 0.25f;
    }
    // Tail: bin 48 (only res==0 threads).
    if (res == 0) {
        const float4 acc = bin_taps(48, feat, sy0, sy1, sx0, sx1,
                                    sly, shy, slx, shx);
        const int base = (4 * c4) * 49 + 48;
        pooled[base]       = acc.x * 0.25f;
        pooled[base + 49]  = acc.y * 0.25f;
        pooled[base + 98]  = acc.z * 0.25f;
        pooled[base + 147] = acc.w * 0.25f;
    }
    __syncthreads();

    // Phase C: stage half-tile into registers once, streaming STG.128 fan-out.
    const float4* __restrict__ psrc = reinterpret_cast<const float4*>(pooled);
    float4 stage[RPT_];
#pragma unroll
    for (int k = 0; k < RPT_; ++k) {
        const int idx = tid + k * 256;
        if (idx < NV_) stage[k] = psrc[idx];
    }

    float4* outv = reinterpret_cast<float4*>(out);
    const int hoff = half * NV_;

    if (m < N_) {
#pragma unroll 1
        for (int q = 0; q < N_ - 1; ++q) {
            int p, slot_o;
            const int hi = N_ - 1 - m;
            if (q < hi) {
                const int j = m + 1 + q;
                p = m * (N_ - 1) - (m * (m - 1)) / 2 + (j - m - 1);
                slot_o = 0;
            } else {
                const int i = q - hi;
                p = i * (N_ - 1) - (i * (i - 1)) / 2 + (m - i - 1);
                slot_o = 1;
            }
            float4* dst = outv + (((size_t)b * P_ + p) * 3 + slot_o) * (CH_ / 4) + hoff;
#pragma unroll
            for (int k = 0; k < RPT_; ++k) {
                const int idx = tid + k * 256;
                if (idx < NV_) stcs4(&dst[idx], stage[k]);
            }
        }
    } else {
        const int p = m - N_;
        float4* dst = outv + (((size_t)b * P_ + p) * 3 + 2) * (CH_ / 4) + hoff;
#pragma unroll
        for (int k = 0; k < RPT_; ++k) {
            const int idx = tid + k * 256;
            if (idx < NV_) stcs4(&dst[idx], stage[k]);
        }
    }
}

// ---------------------------------------------------------------------------
extern "C" void kernel_launch(void* const* d_in, const int* in_sizes, int n_in,
                              void* d_out, int out_size) {
    const float* features = (const float*)d_in[0];  // [B,C,H,W] float32
    const float* boxes    = (const float*)d_in[1];  // [B,N,4]   float32
    float* out = (float*)d_out;

    dim3 tgrid((HW_ + 31) / 32, C_ / 32, B_);
    nchw_to_nhwc_kernel<<<tgrid, dim3(32, 8)>>>(features);

    const int nblocks = 2 * B_ * NROIS_;   // 2400: 192 object CTAs first
    roi_pair_kernel<<<nblocks, 256>>>(boxes, out);
}

// round 14
// speedup vs baseline: 1.1908x; 1.0103x over previous
#include <cuda_runtime.h>
#include <cstdint>

// Problem constants
#define B_   4
#define N_   24
#define C_   256
#define H_   100
#define W_   100
#define OUT_ 7
#define P_   276                      // N*(N-1)/2
#define CH_  (C_ * OUT_ * OUT_)       // 12544 floats per full [C,7,7] chunk
#define HCH_ (CH_ / 2)                // 6272 floats per half-channel chunk
#define HW_  (H_ * W_)
#define SCALE_ 0.25f
#define NROIS_ (N_ + P_)              // 300 rois per batch
#define NV_   (HCH_ / 4)              // 1568 float4 per half tile
#define RPT_  7                       // ceil(1568/256) staging slots

// NHWC scratch for features
__device__ float g_nhwc[(size_t)B_ * HW_ * C_];

__device__ __forceinline__ void stcs4(float4* p, float4 v) {
    asm volatile("st.global.cs.v4.f32 [%0], {%1,%2,%3,%4};"
                 :: "l"(p), "f"(v.x), "f"(v.y), "f"(v.z), "f"(v.w) : "memory");
}

// ---------------------------------------------------------------------------
// Kernel 1: NCHW -> NHWC transpose, float4 stores.
// ---------------------------------------------------------------------------
__global__ void nchw_to_nhwc_kernel(const float* __restrict__ in) {
    __shared__ float tile[32][33];
    const int b   = blockIdx.z;
    const int c0  = blockIdx.y * 32;
    const int hw0 = blockIdx.x * 32;
    const int tx = threadIdx.x, ty = threadIdx.y;   // (32, 8)
    const int tid = ty * 32 + tx;

    const float* src = in + (size_t)b * C_ * HW_;
#pragma unroll
    for (int i = 0; i < 32; i += 8) {
        const int c  = c0 + ty + i;
        const int hw = hw0 + tx;
        float v = 0.0f;
        if (hw < HW_) v = src[(size_t)c * HW_ + hw];
        tile[ty + i][tx] = v;
    }
    __syncthreads();

    const int tx8 = tid & 7;     // float4 channel group
    const int tyy = tid >> 3;    // hw within tile
    const int hw  = hw0 + tyy;
    if (hw < HW_) {
        float4 v;
        v.x = tile[4 * tx8 + 0][tyy];
        v.y = tile[4 * tx8 + 1][tyy];
        v.z = tile[4 * tx8 + 2][tyy];
        v.w = tile[4 * tx8 + 3][tyy];
        float* dst = g_nhwc + (size_t)b * HW_ * C_;
        *reinterpret_cast<float4*>(&dst[(size_t)hw * C_ + c0 + 4 * tx8]) = v;
    }
}

// ---------------------------------------------------------------------------
// Phase-B helper: one bin. Loads ALL 16 taps into locals first (explicit
// load batch -> MLP 16), then does the FMA reduction.
// ---------------------------------------------------------------------------
__device__ __forceinline__ float4 bin_taps(
    int bin, const float4* __restrict__ feat,
    const int* sy0, const int* sy1, const int* sx0, const int* sx1,
    const float* sly, const float* shy, const float* slx, const float* shx)
{
    const int py = bin / OUT_;
    const int px = bin - py * OUT_;

    // Gather sample indices/weights.
    int   rows[4];   // r0a, r1a, r0b, r1b  (2 y-samples x 2 taps)
    float wy[4];
    int   cols[4];   // x0a, x1a, x0b, x1b
    float wx[4];
#pragma unroll
    for (int s = 0; s < 2; ++s) {
        const int yi = 2 * py + s;
        rows[2 * s]     = sy0[yi] * W_;
        rows[2 * s + 1] = sy1[yi] * W_;
        wy[2 * s]       = shy[yi];
        wy[2 * s + 1]   = sly[yi];
        const int xi = 2 * px + s;
        cols[2 * s]     = sx0[xi];
        cols[2 * s + 1] = sx1[xi];
        wx[2 * s]       = shx[xi];
        wx[2 * s + 1]   = slx[xi];
    }

    // Issue all 16 loads back-to-back.
    float4 f[16];
#pragma unroll
    for (int ys = 0; ys < 2; ++ys)          // y sample
#pragma unroll
        for (int yt = 0; yt < 2; ++yt)      // y tap
#pragma unroll
            for (int xs = 0; xs < 2; ++xs)  // x sample
#pragma unroll
                for (int xt = 0; xt < 2; ++xt)  // x tap
                    f[((ys * 2 + yt) * 2 + xs) * 2 + xt] =
                        feat[(size_t)(rows[2 * ys + yt] + cols[2 * xs + xt]) * 64];

    // Reduce.
    float4 acc = make_float4(0.f, 0.f, 0.f, 0.f);
#pragma unroll
    for (int ys = 0; ys < 2; ++ys)
#pragma unroll
        for (int yt = 0; yt < 2; ++yt)
#pragma unroll
            for (int xs = 0; xs < 2; ++xs)
#pragma unroll
                for (int xt = 0; xt < 2; ++xt) {
                    const float w = wy[2 * ys + yt] * wx[2 * xs + xt];
                    const float4 v = f[((ys * 2 + yt) * 2 + xs) * 2 + xt];
                    acc.x += w * v.x;
                    acc.y += w * v.y;
                    acc.z += w * v.z;
                    acc.w += w * v.w;
                }
    return acc;
}

// ---------------------------------------------------------------------------
// Kernel 2: TWO CTAs per roi (one per 128-channel half). 256 threads.
//  launch_bounds(256,3): ~84 regs -> full-bin load batching + cross-bin
//  pipelining. Occupancy is a dead axis for this kernel (R7-R13).
// ---------------------------------------------------------------------------
__global__ __launch_bounds__(256, 3) void roi_pair_kernel(
    const float* __restrict__ boxes,   // [B, N, 4] xyxy, image coords
    float* __restrict__ out)           // [B*P, 3, C, 7, 7]
{
    __shared__ __align__(16) float pooled[HCH_];
    __shared__ int   sy0[14], sy1[14], sx0[14], sx1[14];
    __shared__ float sly[14], shy[14], slx[14], shx[14];

    const int bid  = blockIdx.x;
    const int tid  = threadIdx.x;
    const int r    = bid >> 1;       // roi id 0..1199 (objects first)
    const int half = bid & 1;        // channel half

    int b, m;  // batch, roi index within batch (m < N_: object, else union)
    if (r < B_ * N_) { b = r / N_; m = r % N_; }
    else { const int u = r - B_ * N_; b = u / P_; m = N_ + (u % P_); }

    // Separable sample tables: tid 0..13 -> x, 14..27 -> y.
    if (tid < 28) {
        float x1, y1, x2, y2;
        if (m < N_) {
            const float* bx = boxes + ((size_t)b * N_ + m) * 4;
            x1 = bx[0]; y1 = bx[1]; x2 = bx[2]; y2 = bx[3];
        } else {
            int p = m - N_;
            int i = 0, rem = p, cnt = N_ - 1;
            while (rem >= cnt) { rem -= cnt; ++i; --cnt; }
            const int j = i + 1 + rem;
            const float* ba = boxes + ((size_t)b * N_ + i) * 4;
            const float* bb = boxes + ((size_t)b * N_ + j) * 4;
            x1 = fminf(ba[0], bb[0]);
            y1 = fminf(ba[1], bb[1]);
            x2 = fmaxf(ba[2], bb[2]);
            y2 = fmaxf(ba[3], bb[3]);
        }
        const int  d   = tid % 14;
        const bool isY = (tid >= 14);
        const float c1 = (isY ? y1 : x1) * SCALE_;
        const float c2 = (isY ? y2 : x2) * SCALE_;
        const float sz  = fmaxf(c2 - c1, 1.0f);
        const float bsz = sz * (1.0f / OUT_);
        const float g = (float)(d >> 1) + ((float)(d & 1) + 0.5f) * 0.5f;
        const float X = c1 + g * bsz;
        const int   lim = isY ? H_ : W_;
        const bool  valid = (X > -1.0f) && (X < (float)lim);
        const float Xc  = fminf(fmaxf(X, 0.0f), (float)(lim - 1));
        const float x0f = floorf(Xc);
        float lx = Xc - x0f;
        float hx = 1.0f - lx;
        if (!valid) { lx = 0.0f; hx = 0.0f; }
        const int t0 = (int)x0f;
        const int t1 = min(t0 + 1, lim - 1);
        if (isY) { sy0[d] = t0; sy1[d] = t1; sly[d] = lx; shy[d] = hx; }
        else     { sx0[d] = t0; sx1[d] = t1; slx[d] = lx; shx[d] = hx; }
    }
    __syncthreads();

    // Phase B.
    const int c4   = tid & 31;          // local float4 channel group 0..31
    const int slot = tid >> 5;          // warp id 0..7
    const int oct  = (tid >> 3) & 3;    // lane octet within warp
    const int res  = (slot + oct) & 7;  // bin residue mod 8 (skewed)
    const float4* __restrict__ feat =
        reinterpret_cast<const float4*>(g_nhwc) +
        (size_t)b * HW_ * (C_ / 4) + half * 32 + c4;

    // Bins 8t+res for t in [0,6): max 47 < 48 -> always valid, guard-free.
#pragma unroll
    for (int t = 0; t < 6; ++t) {
        const int bin = 8 * t + res;
        const float4 acc = bin_taps(bin, feat, sy0, sy1, sx0, sx1,
                                    sly, shy, slx, shx);
        const int base = (4 * c4) * 49 + bin;   // conflict-free STS
        pooled[base]       = acc.x * 0.25f;
        pooled[base + 49]  = acc.y * 0.25f;
        pooled[base + 98]  = acc.z * 0.25f;
        pooled[base + 147] = acc.w * 0.25f;
    }
    // Tail: bin 48 (only res==0 threads).
    if (res == 0) {
        const float4 acc = bin_taps(48, feat, sy0, sy1, sx0, sx1,
                                    sly, shy, slx, shx);
        const int base = (4 * c4) * 49 + 48;
        pooled[base]       = acc.x * 0.25f;
        pooled[base + 49]  = acc.y * 0.25f;
        pooled[base + 98]  = acc.z * 0.25f;
        pooled[base + 147] = acc.w * 0.25f;
    }
    __syncthreads();

    // Phase C: stage half-tile into registers once, streaming STG.128 fan-out.
    const float4* __restrict__ psrc = reinterpret_cast<const float4*>(pooled);
    float4 stage[RPT_];
#pragma unroll
    for (int k = 0; k < RPT_; ++k) {
        const int idx = tid + k * 256;
        if (idx < NV_) stage[k] = psrc[idx];
    }

    float4* outv = reinterpret_cast<float4*>(out);
    const int hoff = half * NV_;

    if (m < N_) {
#pragma unroll 1
        for (int q = 0; q < N_ - 1; ++q) {
            int p, slot_o;
            const int hi = N_ - 1 - m;
            if (q < hi) {
                const int j = m + 1 + q;
                p = m * (N_ - 1) - (m * (m - 1)) / 2 + (j - m - 1);
                slot_o = 0;
            } else {
                const int i = q - hi;
                p = i * (N_ - 1) - (i * (i - 1)) / 2 + (m - i - 1);
                slot_o = 1;
            }
            float4* dst = outv + (((size_t)b * P_ + p) * 3 + slot_o) * (CH_ / 4) + hoff;
#pragma unroll
            for (int k = 0; k < RPT_; ++k) {
                const int idx = tid + k * 256;
                if (idx < NV_) stcs4(&dst[idx], stage[k]);
            }
        }
    } else {
        const int p = m - N_;
        float4* dst = outv + (((size_t)b * P_ + p) * 3 + 2) * (CH_ / 4) + hoff;
#pragma unroll
        for (int k = 0; k < RPT_; ++k) {
            const int idx = tid + k * 256;
            if (idx < NV_) stcs4(&dst[idx], stage[k]);
        }
    }
}

// ---------------------------------------------------------------------------
extern "C" void kernel_launch(void* const* d_in, const int* in_sizes, int n_in,
                              void* d_out, int out_size) {
    const float* features = (const float*)d_in[0];  // [B,C,H,W] float32
    const float* boxes    = (const float*)d_in[1];  // [B,N,4]   float32
    float* out = (float*)d_out;

    dim3 tgrid((HW_ + 31) / 32, C_ / 32, B_);
    nchw_to_nhwc_kernel<<<tgrid, dim3(32, 8)>>>(features);

    const int nblocks = 2 * B_ * NROIS_;   // 2400: 192 object CTAs first
    roi_pair_kernel<<<nblocks, 256>>>(boxes, out);
}